// round 14
// baseline (speedup 1.0000x reference)
#include <cuda_runtime.h>
#include <cuda_fp16.h>
#include <math.h>

#define BATCH 16
#define SEQ   512
#define EMB   768
#define HEADS 12
#define HDIM  64
#define ROWS  (BATCH*SEQ)          // 8192
#define BHN   (BATCH*HEADS)        // 192

// fp16 staging globals (natural layouts)
__device__ __half g_inph[ROWS*EMB];          // [m][k]
__device__ __half g_Wh[3*EMB*EMB];           // [w][k][n]
__device__ __half g_Qh[BHN*SEQ*HDIM];        // [bh][s][d], pre-scaled 0.125*log2(e)
__device__ __half g_Kh[BHN*SEQ*HDIM];        // [bh][j][d]  compacted keys
__device__ __half g_Vh[BHN*SEQ*HDIM];        // [bh][j][d]  compacted keys
__device__ int    g_srcs[BATCH*SEQ];         // compacted: global input row (b*512+s)
__device__ int    g_nk[BATCH];               // unmasked key count per batch

// ---------------------------------------------------------------------------
// helpers
// ---------------------------------------------------------------------------
__device__ __forceinline__ void mma16(float c[4],
                                      unsigned a0, unsigned a1, unsigned a2, unsigned a3,
                                      unsigned b0, unsigned b1) {
    asm volatile(
        "mma.sync.aligned.m16n8k16.row.col.f32.f16.f16.f32 "
        "{%0,%1,%2,%3}, {%4,%5,%6,%7}, {%8,%9}, {%0,%1,%2,%3};"
        : "+f"(c[0]), "+f"(c[1]), "+f"(c[2]), "+f"(c[3])
        : "r"(a0), "r"(a1), "r"(a2), "r"(a3), "r"(b0), "r"(b1));
}

__device__ __forceinline__ void ldm4(unsigned& r0, unsigned& r1,
                                     unsigned& r2, unsigned& r3, unsigned a) {
    asm volatile("ldmatrix.sync.aligned.m8n8.x4.shared.b16 {%0,%1,%2,%3}, [%4];"
                 : "=r"(r0), "=r"(r1), "=r"(r2), "=r"(r3) : "r"(a));
}
__device__ __forceinline__ void ldm4t(unsigned& r0, unsigned& r1,
                                      unsigned& r2, unsigned& r3, unsigned a) {
    asm volatile("ldmatrix.sync.aligned.m8n8.x4.trans.shared.b16 {%0,%1,%2,%3}, [%4];"
                 : "=r"(r0), "=r"(r1), "=r"(r2), "=r"(r3) : "r"(a));
}

__device__ __forceinline__ unsigned pkh2(float lo, float hi) {
    unsigned r;
    asm("cvt.rn.f16x2.f32 %0, %1, %2;" : "=r"(r) : "f"(hi), "f"(lo));
    return r;
}

__device__ __forceinline__ float ex2(float x) {
    float r;
    asm("ex2.approx.ftz.f32 %0, %1;" : "=f"(r) : "f"(x));
    return r;
}

__device__ __forceinline__ unsigned smem_u32(const void* p) {
    unsigned a;
    asm("{.reg .u64 t; cvta.to.shared.u64 t, %1; cvt.u32.u64 %0, t;}"
        : "=r"(a) : "l"(p));
    return a;
}

__device__ __forceinline__ void cpa16(unsigned dst, const void* src) {
    asm volatile("cp.async.ca.shared.global [%0], [%1], 16;" :: "r"(dst), "l"(src));
}
#define CP_COMMIT() asm volatile("cp.async.commit_group;" ::: "memory")
#define CP_WAIT(N)  asm volatile("cp.async.wait_group %0;" :: "n"(N) : "memory")

// ---------------------------------------------------------------------------
// merged setup kernel: compact (16 blocks) + cvt_w (1728) + cvt_inp (6144)
// ---------------------------------------------------------------------------
#define NB_CMP  16
#define NB_CVTW (3*576)
#define NB_CVTA 6144
#define NB_SETUP (NB_CMP + NB_CVTW + NB_CVTA)

__global__ __launch_bounds__(256) void setup_kernel(
    const float* __restrict__ inp,  const float* __restrict__ mask,
    const float* __restrict__ Wq,   const float* __restrict__ Wk,
    const float* __restrict__ Wv)
{
    const int blk = blockIdx.x;
    const int tid = threadIdx.x;

    if (blk < NB_CMP) {
        const int b = blk;
        __shared__ int sc[512];
        int f0 = (mask[b*512 + tid]       == 0.0f) ? 1 : 0;
        int f1 = (mask[b*512 + 256 + tid] == 0.0f) ? 1 : 0;
        sc[tid] = f0; sc[tid + 256] = f1;
        __syncthreads();
        for (int off = 1; off < 512; off <<= 1) {
            int i0 = tid, i1 = tid + 256;
            int v0 = sc[i0] + ((i0 >= off) ? sc[i0 - off] : 0);
            int v1 = sc[i1] + ((i1 >= off) ? sc[i1 - off] : 0);
            __syncthreads();
            sc[i0] = v0; sc[i1] = v1;
            __syncthreads();
        }
        int nk = sc[511];
        if (f0) g_srcs[b*512 + sc[tid] - 1]       = b*512 + tid;
        if (f1) g_srcs[b*512 + sc[tid + 256] - 1] = b*512 + 256 + tid;
        if (tid >= nk)       g_srcs[b*512 + tid]       = b*512;
        if (tid + 256 >= nk) g_srcs[b*512 + 256 + tid] = b*512;
        if (tid == 0) g_nk[b] = nk;
    } else if (blk < NB_CMP + NB_CVTW) {
        const int rel = blk - NB_CMP;
        const int w = rel / 576;
        const float* W = (w == 0) ? Wq : (w == 1) ? Wk : Wv;
        int i = (rel % 576) * 256 + tid;
        float4 v = reinterpret_cast<const float4*>(W)[i];
        __half2* o = reinterpret_cast<__half2*>(g_Wh + (long)w*EMB*EMB) + i*2;
        o[0] = __floats2half2_rn(v.x, v.y);
        o[1] = __floats2half2_rn(v.z, v.w);
    } else {
        int i = (blk - NB_CMP - NB_CVTW) * 256 + tid;
        float4 v = reinterpret_cast<const float4*>(inp)[i];
        __half2* o = reinterpret_cast<__half2*>(g_inph) + i*2;
        o[0] = __floats2half2_rn(v.x, v.y);
        o[1] = __floats2half2_rn(v.z, v.w);
    }
}

// ---------------------------------------------------------------------------
// Kernel 1: fused QKV projection. 128 threads, 4 warps of 64x64.
// CTA tile 128x128, K-step 64 (12 iters), 3-stage cp.async pipeline,
// ONE __syncthreads per iteration. 2 CTAs/SM.
// ---------------------------------------------------------------------------
#define AH    72
#define ABUFH (128*AH)             // 9216 halves
#define BHS   136
#define BBUFH (64*BHS)             // 8704 halves
#define PROJ_SMEM ((3*ABUFH + 3*BBUFH)*2)   // 107520 B

__global__ __launch_bounds__(128, 2) void qkv_proj(
    const float* __restrict__ bq, const float* __restrict__ bk,
    const float* __restrict__ bv)
{
    const int z = blockIdx.z;
    const int y = blockIdx.y;
    int bb = 0, tt = 0, nkb = 0;
    if (z > 0) {
        bb = y >> 2; tt = y & 3;
        nkb = g_nk[bb];
        if (tt*128 >= nkb) return;
    }

    const __half* Wp = g_Wh + (long)z*EMB*EMB;
    const float* bias = (z == 0) ? bq : (z == 1) ? bk : bv;

    const int n0 = blockIdx.x * 128;
    const int tid  = threadIdx.x;
    const int lane = tid & 31;
    const int wid  = tid >> 5;
    const int wm = (wid & 1) * 64;      // warp M offset (2 m-warps)
    const int wn = (wid >> 1) * 64;     // warp N offset (2 n-warps)
    const int g  = lane >> 2;
    const int t  = lane & 3;
    const int l15  = lane & 15;
    const int l7   = lane & 7;
    const int hi16 = (lane >> 4) & 1;
    const int hi8  = (lane >> 3) & 1;

    extern __shared__ __half sh[];
    const unsigned sb = smem_u32(sh);
    __shared__ int s_idx[128];

    if (tid < 128)
        s_idx[tid] = (z == 0) ? (y*128 + tid)
                              : g_srcs[bb*512 + tt*128 + tid];
    __syncthreads();

    const unsigned abase = sb + ((wm + l15)*AH + hi16*8)*2;
    const unsigned bbase = sb + 3*ABUFH*2 + ((l7 + hi8*8)*BHS + wn + hi16*8)*2;

    float acc[4][8][4];
    #pragma unroll
    for (int mi = 0; mi < 4; mi++)
        #pragma unroll
        for (int nj = 0; nj < 8; nj++)
            #pragma unroll
            for (int c = 0; c < 4; c++) acc[mi][nj][c] = 0.0f;

    #define ISSUE(IT, BUF) { \
        _Pragma("unroll") for (int i = 0; i < 8; i++) { \
            int f = tid + i*128; int r = f >> 3; int c8 = f & 7; \
            cpa16(sb + ((BUF)*ABUFH + r*AH + c8*8)*2, \
                  g_inph + (long)s_idx[r]*EMB + (IT)*64 + c8*8); } \
        _Pragma("unroll") for (int i = 0; i < 8; i++) { \
            int f = tid + i*128; int r = f >> 4; int c8 = f & 15; \
            cpa16(sb + (3*ABUFH*2 + ((BUF)*BBUFH + r*BHS + c8*8)*2)), \
                  Wp + ((IT)*64 + r)*EMB + n0 + c8*8); } \
        CP_COMMIT(); }
    // (note: macro above kept textually aligned with byte addressing below)
    #undef ISSUE
    #define ISSUE(IT, BUF) { \
        _Pragma("unroll") for (int i = 0; i < 8; i++) { \
            int f = tid + i*128; int r = f >> 3; int c8 = f & 7; \
            cpa16(sb + ((BUF)*ABUFH + r*AH + c8*8)*2, \
                  g_inph + (long)s_idx[r]*EMB + (IT)*64 + c8*8); } \
        _Pragma("unroll") for (int i = 0; i < 8; i++) { \
            int f = tid + i*128; int r = f >> 4; int c8 = f & 15; \
            cpa16(sb + (3*ABUFH + (BUF)*BBUFH + r*BHS + c8*8)*2, \
                  Wp + ((IT)*64 + r)*EMB + n0 + c8*8); } \
        CP_COMMIT(); }

    ISSUE(0, 0);
    ISSUE(1, 1);

    for (int it = 0; it < 12; it++) {
        CP_WAIT(1);
        __syncthreads();

        // stage it+2 into buffer (it+2)%3 — consumed at iter it-1, safe now
        if (it + 2 < 12) {
            int nb = (it + 2) % 3;
            ISSUE(it + 2, nb);
        }

        const int buf = it % 3;
        const unsigned ab = abase + buf*ABUFH*2;
        const unsigned bb2 = bbase + buf*BBUFH*2;

        #pragma unroll
        for (int s = 0; s < 4; s++) {
            unsigned a[4][4];
            #pragma unroll
            for (int mi = 0; mi < 4; mi++)
                ldm4(a[mi][0], a[mi][1], a[mi][2], a[mi][3],
                     ab + (mi*16*AH + s*16)*2);
            unsigned b[8][2];
            #pragma unroll
            for (int p = 0; p < 4; p++) {
                unsigned r0, r1, r2, r3;
                ldm4t(r0, r1, r2, r3, bb2 + (s*16*BHS + p*16)*2);
                b[2*p][0] = r0; b[2*p][1] = r1;
                b[2*p+1][0] = r2; b[2*p+1][1] = r3;
            }
            #pragma unroll
            for (int mi = 0; mi < 4; mi++)
                #pragma unroll
                for (int nj = 0; nj < 8; nj++)
                    mma16(acc[mi][nj], a[mi][0], a[mi][1], a[mi][2], a[mi][3],
                          b[nj][0], b[nj][1]);
        }
    }
    #undef ISSUE

    // Epilogue: half2 stores (n even, pairs within one head).
    if (z == 0) {
        const float qs = 0.18033688f;   // 0.125 * log2(e)
        #pragma unroll
        for (int mi = 0; mi < 4; mi++) {
            #pragma unroll
            for (int nj = 0; nj < 8; nj++) {
                int n = n0 + wn + nj*8 + 2*t;
                int h = n >> 6, d = n & 63;
                float b0v = bias[n], b1v = bias[n+1];
                int row = y*128 + wm + mi*16 + g;
                int b = row >> 9, s = row & 511;
                __half2* p0 = reinterpret_cast<__half2*>(
                    &g_Qh[((long)(b*HEADS + h)*SEQ + s)*HDIM + d]);
                *p0 = __floats2half2_rn((acc[mi][nj][0] + b0v)*qs,
                                        (acc[mi][nj][1] + b1v)*qs);
                int row2 = row + 8;
                int b2 = row2 >> 9, s2 = row2 & 511;
                __half2* p1 = reinterpret_cast<__half2*>(
                    &g_Qh[((long)(b2*HEADS + h)*SEQ + s2)*HDIM + d]);
                *p1 = __floats2half2_rn((acc[mi][nj][2] + b0v)*qs,
                                        (acc[mi][nj][3] + b1v)*qs);
            }
        }
    } else {
        __half* outh = (z == 1) ? g_Kh : g_Vh;
        #pragma unroll
        for (int mi = 0; mi < 4; mi++) {
            #pragma unroll
            for (int nj = 0; nj < 8; nj++) {
                int n = n0 + wn + nj*8 + 2*t;
                int h = n >> 6, d = n & 63;
                float b0v = bias[n], b1v = bias[n+1];
                int j0 = tt*128 + wm + mi*16 + g;
                if (j0 < nkb) {
                    __half2* p0 = reinterpret_cast<__half2*>(
                        &outh[((long)(bb*HEADS + h)*SEQ + j0)*HDIM + d]);
                    *p0 = __floats2half2_rn(acc[mi][nj][0] + b0v,
                                            acc[mi][nj][1] + b1v);
                }
                int j1 = j0 + 8;
                if (j1 < nkb) {
                    __half2* p1 = reinterpret_cast<__half2*>(
                        &outh[((long)(bb*HEADS + h)*SEQ + j1)*HDIM + d]);
                    *p1 = __floats2half2_rn(acc[mi][nj][2] + b0v,
                                            acc[mi][nj][3] + b1v);
                }
            }
        }
    }
}

// ---------------------------------------------------------------------------
// Kernel 2: flash attention over COMPACTED keys. 128 threads, 4 warps x 32
// query rows. 3-stage K/V pipeline, ONE sync per chunk. 2 CTAs/SM.
// ---------------------------------------------------------------------------
#define QH    72
#define QBUFH (128*QH)             // 9216
#define KH    72
#define KBUFH (64*KH)              // 4608
#define VH    72
#define VBUFH (64*VH)              // 4608
#define ATTN_SMEM ((QBUFH + 3*KBUFH + 3*VBUFH)*2)   // 73728 B

__global__ __launch_bounds__(128, 2) void attn_kernel(float* __restrict__ out)
{
    const int b  = blockIdx.z;
    const int h  = blockIdx.y;
    const int bh = b*HEADS + h;
    const int q0 = blockIdx.x * 128;
    const int tid  = threadIdx.x;
    const int lane = tid & 31;
    const int wid  = tid >> 5;
    const int wm = wid * 32;           // warp covers 32 query rows
    const int g  = lane >> 2;
    const int t  = lane & 3;
    const int l15  = lane & 15;
    const int l7   = lane & 7;
    const int hi16 = (lane >> 4) & 1;
    const int hi8  = (lane >> 3) & 1;

    const int nk  = g_nk[b];
    const int nch = (nk + 63) >> 6;

    extern __shared__ __half sh[];
    const unsigned sb = smem_u32(sh);

    const __half* Qg = g_Qh + (long)bh*SEQ*HDIM + (long)q0*HDIM;
    const __half* Kg = g_Kh + (long)bh*SEQ*HDIM;
    const __half* Vg = g_Vh + (long)bh*SEQ*HDIM;

    const unsigned qbase = sb + ((wm + l15)*QH + hi16*8)*2;
    const unsigned kbase = sb + QBUFH*2 + ((l7 + hi16*8)*KH + hi8*8)*2;
    const unsigned vbase = sb + (QBUFH + 3*KBUFH)*2 + ((l7 + hi8*8)*VH + hi16*8)*2;

    #define ISSUE_KV(KC, BUF) { \
        _Pragma("unroll") for (int i = 0; i < 4; i++) { \
            int f = tid + i*128; int r = f >> 3; int c8 = f & 7; \
            cpa16(sb + (QBUFH + (BUF)*KBUFH + r*KH + c8*8)*2, \
                  Kg + ((KC)*64 + r)*HDIM + c8*8); } \
        _Pragma("unroll") for (int i = 0; i < 4; i++) { \
            int f = tid + i*128; int r = f >> 3; int c8 = f & 7; \
            cpa16(sb + (QBUFH + 3*KBUFH + (BUF)*VBUFH + r*VH + c8*8)*2, \
                  Vg + ((KC)*64 + r)*HDIM + c8*8); } \
        CP_COMMIT(); }

    // Prologue: Q + chunk0 (group 0), chunk1 (group 1).
    {
        #pragma unroll
        for (int i = 0; i < 8; i++) {
            int f = tid + i*128; int r = f >> 3; int c8 = f & 7;
            cpa16(sb + (r*QH + c8*8)*2, Qg + r*HDIM + c8*8);
        }
        ISSUE_KV(0, 0);
        ISSUE_KV(1, 1);
    }

    float oacc[2][8][4];
    #pragma unroll
    for (int mh = 0; mh < 2; mh++)
        #pragma unroll
        for (int dj = 0; dj < 8; dj++)
            #pragma unroll
            for (int c = 0; c < 4; c++) oacc[mh][dj][c] = 0.0f;
    float lm[2][2] = {{0.0f, 0.0f}, {0.0f, 0.0f}};
    const unsigned FULL = 0xffffffffu;

    for (int kc = 0; kc < nch; kc++) {
        CP_WAIT(1);
        __syncthreads();

        // stage kc+2 into buffer (kc+2)%3 — consumed at chunk kc-1, safe now
        if (kc + 2 < nch) {
            int nb = (kc + 2) % 3;
            ISSUE_KV(kc + 2, nb);
        }

        const int buf = kc % 3;
        const unsigned kb = kbase + buf*KBUFH*2;
        const unsigned vb = vbase + buf*VBUFH*2;

        // ---- S' = Q K^T (Q pre-scaled by 0.125*log2e) ----
        float sacc[2][8][4];
        #pragma unroll
        for (int mh = 0; mh < 2; mh++)
            #pragma unroll
            for (int nj = 0; nj < 8; nj++)
                #pragma unroll
                for (int c = 0; c < 4; c++) sacc[mh][nj][c] = 0.0f;

        #pragma unroll
        for (int s = 0; s < 4; s++) {
            unsigned kr[16];
            #pragma unroll
            for (int p = 0; p < 4; p++)
                ldm4(kr[4*p], kr[4*p+1], kr[4*p+2], kr[4*p+3],
                     kb + (p*16*KH + s*16)*2);
            #pragma unroll
            for (int mh = 0; mh < 2; mh++) {
                unsigned a0, a1, a2, a3;
                ldm4(a0, a1, a2, a3, qbase + (mh*16*QH + s*16)*2);
                #pragma unroll
                for (int p = 0; p < 4; p++) {
                    mma16(sacc[mh][2*p],   a0, a1, a2, a3, kr[4*p],   kr[4*p+1]);
                    mma16(sacc[mh][2*p+1], a0, a1, a2, a3, kr[4*p+2], kr[4*p+3]);
                }
            }
        }

        // ---- P = exp2(S'); tail chunk zeroes padded keys ----
        #pragma unroll
        for (int mh = 0; mh < 2; mh++) {
            float rs0 = 0.0f, rs1 = 0.0f;
            if (kc + 1 == nch) {
                #pragma unroll
                for (int nj = 0; nj < 8; nj++) {
                    int key = kc*64 + nj*8 + 2*t;
                    float p0 = (key   < nk) ? ex2(sacc[mh][nj][0]) : 0.0f;
                    float p1 = (key+1 < nk) ? ex2(sacc[mh][nj][1]) : 0.0f;
                    float p2 = (key   < nk) ? ex2(sacc[mh][nj][2]) : 0.0f;
                    float p3 = (key+1 < nk) ? ex2(sacc[mh][nj][3]) : 0.0f;
                    sacc[mh][nj][0] = p0; sacc[mh][nj][1] = p1;
                    sacc[mh][nj][2] = p2; sacc[mh][nj][3] = p3;
                    rs0 += p0 + p1; rs1 += p2 + p3;
                }
            } else {
                #pragma unroll
                for (int nj = 0; nj < 8; nj++) {
                    float p0 = ex2(sacc[mh][nj][0]);
                    float p1 = ex2(sacc[mh][nj][1]);
                    float p2 = ex2(sacc[mh][nj][2]);
                    float p3 = ex2(sacc[mh][nj][3]);
                    sacc[mh][nj][0] = p0; sacc[mh][nj][1] = p1;
                    sacc[mh][nj][2] = p2; sacc[mh][nj][3] = p3;
                    rs0 += p0 + p1; rs1 += p2 + p3;
                }
            }
            lm[mh][0] += rs0;
            lm[mh][1] += rs1;
        }

        // ---- O += P V ----
        #pragma unroll
        for (int s = 0; s < 4; s++) {
            unsigned vr[16];
            #pragma unroll
            for (int p = 0; p < 4; p++)
                ldm4t(vr[4*p], vr[4*p+1], vr[4*p+2], vr[4*p+3],
                      vb + (s*16*VH + p*16)*2);
            #pragma unroll
            for (int mh = 0; mh < 2; mh++) {
                unsigned a0 = pkh2(sacc[mh][2*s][0],   sacc[mh][2*s][1]);
                unsigned a1 = pkh2(sacc[mh][2*s][2],   sacc[mh][2*s][3]);
                unsigned a2 = pkh2(sacc[mh][2*s+1][0], sacc[mh][2*s+1][1]);
                unsigned a3 = pkh2(sacc[mh][2*s+1][2], sacc[mh][2*s+1][3]);
                #pragma unroll
                for (int p = 0; p < 4; p++) {
                    mma16(oacc[mh][2*p],   a0, a1, a2, a3, vr[4*p],   vr[4*p+1]);
                    mma16(oacc[mh][2*p+1], a0, a1, a2, a3, vr[4*p+2], vr[4*p+3]);
                }
            }
        }
    }
    #undef ISSUE_KV

    // ---- normalize and write out (B, S, H*D), float2 stores ----
    #pragma unroll
    for (int mh = 0; mh < 2; mh++) {
        float la = lm[mh][0], lb = lm[mh][1];
        la += __shfl_xor_sync(FULL, la, 1);
        la += __shfl_xor_sync(FULL, la, 2);
        lb += __shfl_xor_sync(FULL, lb, 1);
        lb += __shfl_xor_sync(FULL, lb, 2);
        float inv0 = 1.0f / la;
        float inv1 = 1.0f / lb;

        const int qa = q0 + wm + mh*16 + g;
        const int qb = qa + 8;
        #pragma unroll
        for (int dj = 0; dj < 8; dj++) {
            int d = h*HDIM + dj*8 + 2*t;
            float2 v0 = make_float2(oacc[mh][dj][0]*inv0, oacc[mh][dj][1]*inv0);
            float2 v1 = make_float2(oacc[mh][dj][2]*inv1, oacc[mh][dj][3]*inv1);
            *reinterpret_cast<float2*>(&out[(b*SEQ + qa)*EMB + d]) = v0;
            *reinterpret_cast<float2*>(&out[(b*SEQ + qb)*EMB + d]) = v1;
        }
    }
}

// ---------------------------------------------------------------------------
extern "C" void kernel_launch(void* const* d_in, const int* in_sizes, int n_in,
                              void* d_out, int out_size)
{
    const float* inp  = (const float*)d_in[0];
    const float* mask = (const float*)d_in[1];
    const float* Wq   = (const float*)d_in[2];
    const float* bq   = (const float*)d_in[3];
    const float* Wk   = (const float*)d_in[4];
    const float* bk   = (const float*)d_in[5];
    const float* Wv   = (const float*)d_in[6];
    const float* bv   = (const float*)d_in[7];
    float* out = (float*)d_out;

    cudaFuncSetAttribute(qkv_proj,
                         cudaFuncAttributeMaxDynamicSharedMemorySize,
                         (int)PROJ_SMEM);
    cudaFuncSetAttribute(attn_kernel,
                         cudaFuncAttributeMaxDynamicSharedMemorySize,
                         (int)ATTN_SMEM);

    setup_kernel<<<NB_SETUP, 256>>>(inp, mask, Wq, Wk, Wv);

    dim3 gproj(EMB/128, 64, 3);
    qkv_proj<<<gproj, 128, PROJ_SMEM>>>(bq, bk, bv);

    dim3 gattn(SEQ/128, HEADS, BATCH);
    attn_kernel<<<gattn, 128, ATTN_SMEM>>>(out);
}

// round 15
// speedup vs baseline: 1.0153x; 1.0153x over previous
#include <cuda_runtime.h>
#include <cuda_fp16.h>
#include <math.h>

#define BATCH 16
#define SEQ   512
#define EMB   768
#define HEADS 12
#define HDIM  64
#define ROWS  (BATCH*SEQ)          // 8192
#define BHN   (BATCH*HEADS)        // 192

// fp16 staging globals (natural layouts)
__device__ __half g_inph[ROWS*EMB];          // [m][k]
__device__ __half g_Wh[3*EMB*EMB];           // [w][k][n]
__device__ __half g_Qh[BHN*SEQ*HDIM];        // [bh][s][d], pre-scaled 0.125*log2(e)
__device__ __half g_Kh[BHN*SEQ*HDIM];        // [bh][j][d]  compacted keys
__device__ __half g_Vh[BHN*SEQ*HDIM];        // [bh][j][d]  compacted keys
__device__ int    g_srcs[BATCH*SEQ];         // compacted: global input row (b*512+s)
__device__ int    g_nk[BATCH];               // unmasked key count per batch

// ---------------------------------------------------------------------------
// helpers
// ---------------------------------------------------------------------------
__device__ __forceinline__ void mma16(float c[4],
                                      unsigned a0, unsigned a1, unsigned a2, unsigned a3,
                                      unsigned b0, unsigned b1) {
    asm volatile(
        "mma.sync.aligned.m16n8k16.row.col.f32.f16.f16.f32 "
        "{%0,%1,%2,%3}, {%4,%5,%6,%7}, {%8,%9}, {%0,%1,%2,%3};"
        : "+f"(c[0]), "+f"(c[1]), "+f"(c[2]), "+f"(c[3])
        : "r"(a0), "r"(a1), "r"(a2), "r"(a3), "r"(b0), "r"(b1));
}

__device__ __forceinline__ void ldm4(unsigned& r0, unsigned& r1,
                                     unsigned& r2, unsigned& r3, unsigned a) {
    asm volatile("ldmatrix.sync.aligned.m8n8.x4.shared.b16 {%0,%1,%2,%3}, [%4];"
                 : "=r"(r0), "=r"(r1), "=r"(r2), "=r"(r3) : "r"(a));
}
__device__ __forceinline__ void ldm4t(unsigned& r0, unsigned& r1,
                                      unsigned& r2, unsigned& r3, unsigned a) {
    asm volatile("ldmatrix.sync.aligned.m8n8.x4.trans.shared.b16 {%0,%1,%2,%3}, [%4];"
                 : "=r"(r0), "=r"(r1), "=r"(r2), "=r"(r3) : "r"(a));
}

__device__ __forceinline__ unsigned pkh2(float lo, float hi) {
    unsigned r;
    asm("cvt.rn.f16x2.f32 %0, %1, %2;" : "=r"(r) : "f"(hi), "f"(lo));
    return r;
}

__device__ __forceinline__ float ex2(float x) {
    float r;
    asm("ex2.approx.ftz.f32 %0, %1;" : "=f"(r) : "f"(x));
    return r;
}

__device__ __forceinline__ unsigned smem_u32(const void* p) {
    unsigned a;
    asm("{.reg .u64 t; cvta.to.shared.u64 t, %1; cvt.u32.u64 %0, t;}"
        : "=r"(a) : "l"(p));
    return a;
}

__device__ __forceinline__ void cpa16(unsigned dst, const void* src) {
    asm volatile("cp.async.ca.shared.global [%0], [%1], 16;" :: "r"(dst), "l"(src));
}
#define CP_COMMIT() asm volatile("cp.async.commit_group;" ::: "memory")
#define CP_WAIT(N)  asm volatile("cp.async.wait_group %0;" :: "n"(N) : "memory")

// ---------------------------------------------------------------------------
// merged setup kernel: compact (16 blocks) + cvt_w (1728) + cvt_inp (6144)
// ---------------------------------------------------------------------------
#define NB_CMP  16
#define NB_CVTW (3*576)
#define NB_CVTA 6144
#define NB_SETUP (NB_CMP + NB_CVTW + NB_CVTA)

__global__ __launch_bounds__(256) void setup_kernel(
    const float* __restrict__ inp,  const float* __restrict__ mask,
    const float* __restrict__ Wq,   const float* __restrict__ Wk,
    const float* __restrict__ Wv)
{
    const int blk = blockIdx.x;
    const int tid = threadIdx.x;

    if (blk < NB_CMP) {
        const int b = blk;
        __shared__ int sc[512];
        int f0 = (mask[b*512 + tid]       == 0.0f) ? 1 : 0;
        int f1 = (mask[b*512 + 256 + tid] == 0.0f) ? 1 : 0;
        sc[tid] = f0; sc[tid + 256] = f1;
        __syncthreads();
        for (int off = 1; off < 512; off <<= 1) {
            int i0 = tid, i1 = tid + 256;
            int v0 = sc[i0] + ((i0 >= off) ? sc[i0 - off] : 0);
            int v1 = sc[i1] + ((i1 >= off) ? sc[i1 - off] : 0);
            __syncthreads();
            sc[i0] = v0; sc[i1] = v1;
            __syncthreads();
        }
        int nk = sc[511];
        if (f0) g_srcs[b*512 + sc[tid] - 1]       = b*512 + tid;
        if (f1) g_srcs[b*512 + sc[tid + 256] - 1] = b*512 + 256 + tid;
        if (tid >= nk)       g_srcs[b*512 + tid]       = b*512;
        if (tid + 256 >= nk) g_srcs[b*512 + 256 + tid] = b*512;
        if (tid == 0) g_nk[b] = nk;
    } else if (blk < NB_CMP + NB_CVTW) {
        const int rel = blk - NB_CMP;
        const int w = rel / 576;
        const float* W = (w == 0) ? Wq : (w == 1) ? Wk : Wv;
        int i = (rel % 576) * 256 + tid;
        float4 v = reinterpret_cast<const float4*>(W)[i];
        __half2* o = reinterpret_cast<__half2*>(g_Wh + (long)w*EMB*EMB) + i*2;
        o[0] = __floats2half2_rn(v.x, v.y);
        o[1] = __floats2half2_rn(v.z, v.w);
    } else {
        int i = (blk - NB_CMP - NB_CVTW) * 256 + tid;
        float4 v = reinterpret_cast<const float4*>(inp)[i];
        __half2* o = reinterpret_cast<__half2*>(g_inph) + i*2;
        o[0] = __floats2half2_rn(v.x, v.y);
        o[1] = __floats2half2_rn(v.z, v.w);
    }
}

// ---------------------------------------------------------------------------
// Kernel 1: fused QKV projection. 128 threads, 4 warps of 64x64.
// CTA tile 128x128, K-step 64 (12 iters), 3-stage cp.async ring with
// R12 ordering (MMA first, staging at bottom), ONE sync/iter. 2 CTAs/SM.
// ---------------------------------------------------------------------------
#define AH    72
#define ABUFH (128*AH)             // 9216 halves
#define BHS   136
#define BBUFH (64*BHS)             // 8704 halves
#define PROJ_SMEM ((3*ABUFH + 3*BBUFH)*2)   // 107520 B

__global__ __launch_bounds__(128, 2) void qkv_proj(
    const float* __restrict__ bq, const float* __restrict__ bk,
    const float* __restrict__ bv)
{
    const int z = blockIdx.z;
    const int y = blockIdx.y;
    int bb = 0, tt = 0, nkb = 0;
    if (z > 0) {
        bb = y >> 2; tt = y & 3;
        nkb = g_nk[bb];
        if (tt*128 >= nkb) return;
    }

    const __half* Wp = g_Wh + (long)z*EMB*EMB;
    const float* bias = (z == 0) ? bq : (z == 1) ? bk : bv;

    const int n0 = blockIdx.x * 128;
    const int tid  = threadIdx.x;
    const int lane = tid & 31;
    const int wid  = tid >> 5;
    const int wm = (wid & 1) * 64;      // warp M offset (2 m-warps)
    const int wn = (wid >> 1) * 64;     // warp N offset (2 n-warps)
    const int g  = lane >> 2;
    const int t  = lane & 3;
    const int l15  = lane & 15;
    const int l7   = lane & 7;
    const int hi16 = (lane >> 4) & 1;
    const int hi8  = (lane >> 3) & 1;

    extern __shared__ __half sh[];
    const unsigned sb = smem_u32(sh);
    __shared__ int s_idx[128];

    if (tid < 128)
        s_idx[tid] = (z == 0) ? (y*128 + tid)
                              : g_srcs[bb*512 + tt*128 + tid];
    __syncthreads();

    const unsigned abase = sb + ((wm + l15)*AH + hi16*8)*2;
    const unsigned bbase = sb + 3*ABUFH*2 + ((l7 + hi8*8)*BHS + wn + hi16*8)*2;

    float acc[4][8][4];
    #pragma unroll
    for (int mi = 0; mi < 4; mi++)
        #pragma unroll
        for (int nj = 0; nj < 8; nj++)
            #pragma unroll
            for (int c = 0; c < 4; c++) acc[mi][nj][c] = 0.0f;

    #define ISSUE(IT, BUF) { \
        _Pragma("unroll") for (int i = 0; i < 8; i++) { \
            int f = tid + i*128; int r = f >> 3; int c8 = f & 7; \
            cpa16(sb + ((BUF)*ABUFH + r*AH + c8*8)*2, \
                  g_inph + (long)s_idx[r]*EMB + (IT)*64 + c8*8); } \
        _Pragma("unroll") for (int i = 0; i < 8; i++) { \
            int f = tid + i*128; int r = f >> 4; int c8 = f & 15; \
            cpa16(sb + (3*ABUFH + (BUF)*BBUFH + r*BHS + c8*8)*2, \
                  Wp + ((IT)*64 + r)*EMB + n0 + c8*8); } \
        CP_COMMIT(); }

    ISSUE(0, 0);
    ISSUE(1, 1);

    for (int it = 0; it < 12; it++) {
        if (it < 10) CP_WAIT(1); else CP_WAIT(0);
        __syncthreads();

        const int buf = it % 3;
        const unsigned ab = abase + buf*ABUFH*2;
        const unsigned bb2 = bbase + buf*BBUFH*2;

        #pragma unroll
        for (int s = 0; s < 4; s++) {
            unsigned a[4][4];
            #pragma unroll
            for (int mi = 0; mi < 4; mi++)
                ldm4(a[mi][0], a[mi][1], a[mi][2], a[mi][3],
                     ab + (mi*16*AH + s*16)*2);
            unsigned b[8][2];
            #pragma unroll
            for (int p = 0; p < 4; p++) {
                unsigned r0, r1, r2, r3;
                ldm4t(r0, r1, r2, r3, bb2 + (s*16*BHS + p*16)*2);
                b[2*p][0] = r0; b[2*p][1] = r1;
                b[2*p+1][0] = r2; b[2*p+1][1] = r3;
            }
            #pragma unroll
            for (int mi = 0; mi < 4; mi++)
                #pragma unroll
                for (int nj = 0; nj < 8; nj++)
                    mma16(acc[mi][nj], a[mi][0], a[mi][1], a[mi][2], a[mi][3],
                          b[nj][0], b[nj][1]);
        }

        // stage it+2 into ring slot (it+2)%3: last read in iter it-1,
        // which all warps finished before this iteration's barrier.
        if (it + 2 < 12) {
            ISSUE(it + 2, (it + 2) % 3);
        }
    }
    #undef ISSUE

    // Epilogue: half2 stores (n even, pairs within one head).
    if (z == 0) {
        const float qs = 0.18033688f;   // 0.125 * log2(e)
        #pragma unroll
        for (int mi = 0; mi < 4; mi++) {
            #pragma unroll
            for (int nj = 0; nj < 8; nj++) {
                int n = n0 + wn + nj*8 + 2*t;
                int h = n >> 6, d = n & 63;
                float b0v = bias[n], b1v = bias[n+1];
                int row = y*128 + wm + mi*16 + g;
                int b = row >> 9, s = row & 511;
                __half2* p0 = reinterpret_cast<__half2*>(
                    &g_Qh[((long)(b*HEADS + h)*SEQ + s)*HDIM + d]);
                *p0 = __floats2half2_rn((acc[mi][nj][0] + b0v)*qs,
                                        (acc[mi][nj][1] + b1v)*qs);
                int row2 = row + 8;
                int b2 = row2 >> 9, s2 = row2 & 511;
                __half2* p1 = reinterpret_cast<__half2*>(
                    &g_Qh[((long)(b2*HEADS + h)*SEQ + s2)*HDIM + d]);
                *p1 = __floats2half2_rn((acc[mi][nj][2] + b0v)*qs,
                                        (acc[mi][nj][3] + b1v)*qs);
            }
        }
    } else {
        __half* outh = (z == 1) ? g_Kh : g_Vh;
        #pragma unroll
        for (int mi = 0; mi < 4; mi++) {
            #pragma unroll
            for (int nj = 0; nj < 8; nj++) {
                int n = n0 + wn + nj*8 + 2*t;
                int h = n >> 6, d = n & 63;
                float b0v = bias[n], b1v = bias[n+1];
                int j0 = tt*128 + wm + mi*16 + g;
                if (j0 < nkb) {
                    __half2* p0 = reinterpret_cast<__half2*>(
                        &outh[((long)(bb*HEADS + h)*SEQ + j0)*HDIM + d]);
                    *p0 = __floats2half2_rn(acc[mi][nj][0] + b0v,
                                            acc[mi][nj][1] + b1v);
                }
                int j1 = j0 + 8;
                if (j1 < nkb) {
                    __half2* p1 = reinterpret_cast<__half2*>(
                        &outh[((long)(bb*HEADS + h)*SEQ + j1)*HDIM + d]);
                    *p1 = __floats2half2_rn(acc[mi][nj][2] + b0v,
                                            acc[mi][nj][3] + b1v);
                }
            }
        }
    }
}

// ---------------------------------------------------------------------------
// Kernel 2: flash attention over COMPACTED keys. 128 threads, 4 warps x 32
// query rows. 3-stage K/V ring with R12 ordering, ONE sync/chunk. 2 CTAs/SM.
// ---------------------------------------------------------------------------
#define QH    72
#define QBUFH (128*QH)             // 9216
#define KH    72
#define KBUFH (64*KH)              // 4608
#define VH    72
#define VBUFH (64*VH)              // 4608
#define ATTN_SMEM ((QBUFH + 3*KBUFH + 3*VBUFH)*2)   // 73728 B

__global__ __launch_bounds__(128, 2) void attn_kernel(float* __restrict__ out)
{
    const int b  = blockIdx.z;
    const int h  = blockIdx.y;
    const int bh = b*HEADS + h;
    const int q0 = blockIdx.x * 128;
    const int tid  = threadIdx.x;
    const int lane = tid & 31;
    const int wid  = tid >> 5;
    const int wm = wid * 32;           // warp covers 32 query rows
    const int g  = lane >> 2;
    const int t  = lane & 3;
    const int l15  = lane & 15;
    const int l7   = lane & 7;
    const int hi16 = (lane >> 4) & 1;
    const int hi8  = (lane >> 3) & 1;

    const int nk  = g_nk[b];
    const int nch = (nk + 63) >> 6;

    extern __shared__ __half sh[];
    const unsigned sb = smem_u32(sh);

    const __half* Qg = g_Qh + (long)bh*SEQ*HDIM + (long)q0*HDIM;
    const __half* Kg = g_Kh + (long)bh*SEQ*HDIM;
    const __half* Vg = g_Vh + (long)bh*SEQ*HDIM;

    const unsigned qbase = sb + ((wm + l15)*QH + hi16*8)*2;
    const unsigned kbase = sb + QBUFH*2 + ((l7 + hi16*8)*KH + hi8*8)*2;
    const unsigned vbase = sb + (QBUFH + 3*KBUFH)*2 + ((l7 + hi8*8)*VH + hi16*8)*2;

    #define ISSUE_KV(KC, BUF) { \
        _Pragma("unroll") for (int i = 0; i < 4; i++) { \
            int f = tid + i*128; int r = f >> 3; int c8 = f & 7; \
            cpa16(sb + (QBUFH + (BUF)*KBUFH + r*KH + c8*8)*2, \
                  Kg + ((KC)*64 + r)*HDIM + c8*8); } \
        _Pragma("unroll") for (int i = 0; i < 4; i++) { \
            int f = tid + i*128; int r = f >> 3; int c8 = f & 7; \
            cpa16(sb + (QBUFH + 3*KBUFH + (BUF)*VBUFH + r*VH + c8*8)*2, \
                  Vg + ((KC)*64 + r)*HDIM + c8*8); } \
        CP_COMMIT(); }

    // Prologue: Q + chunk0 (group 0), chunk1 (group 1).
    {
        #pragma unroll
        for (int i = 0; i < 8; i++) {
            int f = tid + i*128; int r = f >> 3; int c8 = f & 7;
            cpa16(sb + (r*QH + c8*8)*2, Qg + r*HDIM + c8*8);
        }
        ISSUE_KV(0, 0);
        ISSUE_KV(1, 1);
    }

    float oacc[2][8][4];
    #pragma unroll
    for (int mh = 0; mh < 2; mh++)
        #pragma unroll
        for (int dj = 0; dj < 8; dj++)
            #pragma unroll
            for (int c = 0; c < 4; c++) oacc[mh][dj][c] = 0.0f;
    float lm[2][2] = {{0.0f, 0.0f}, {0.0f, 0.0f}};
    const unsigned FULL = 0xffffffffu;

    for (int kc = 0; kc < nch; kc++) {
        if (kc + 2 < nch) CP_WAIT(1); else CP_WAIT(0);
        __syncthreads();

        const int buf = kc % 3;
        const unsigned kb = kbase + buf*KBUFH*2;
        const unsigned vb = vbase + buf*VBUFH*2;

        // ---- S' = Q K^T (Q pre-scaled by 0.125*log2e) ----
        float sacc[2][8][4];
        #pragma unroll
        for (int mh = 0; mh < 2; mh++)
            #pragma unroll
            for (int nj = 0; nj < 8; nj++)
                #pragma unroll
                for (int c = 0; c < 4; c++) sacc[mh][nj][c] = 0.0f;

        #pragma unroll
        for (int s = 0; s < 4; s++) {
            unsigned kr[16];
            #pragma unroll
            for (int p = 0; p < 4; p++)
                ldm4(kr[4*p], kr[4*p+1], kr[4*p+2], kr[4*p+3],
                     kb + (p*16*KH + s*16)*2);
            #pragma unroll
            for (int mh = 0; mh < 2; mh++) {
                unsigned a0, a1, a2, a3;
                ldm4(a0, a1, a2, a3, qbase + (mh*16*QH + s*16)*2);
                #pragma unroll
                for (int p = 0; p < 4; p++) {
                    mma16(sacc[mh][2*p],   a0, a1, a2, a3, kr[4*p],   kr[4*p+1]);
                    mma16(sacc[mh][2*p+1], a0, a1, a2, a3, kr[4*p+2], kr[4*p+3]);
                }
            }
        }

        // ---- P = exp2(S'); tail chunk zeroes padded keys ----
        #pragma unroll
        for (int mh = 0; mh < 2; mh++) {
            float rs0 = 0.0f, rs1 = 0.0f;
            if (kc + 1 == nch) {
                #pragma unroll
                for (int nj = 0; nj < 8; nj++) {
                    int key = kc*64 + nj*8 + 2*t;
                    float p0 = (key   < nk) ? ex2(sacc[mh][nj][0]) : 0.0f;
                    float p1 = (key+1 < nk) ? ex2(sacc[mh][nj][1]) : 0.0f;
                    float p2 = (key   < nk) ? ex2(sacc[mh][nj][2]) : 0.0f;
                    float p3 = (key+1 < nk) ? ex2(sacc[mh][nj][3]) : 0.0f;
                    sacc[mh][nj][0] = p0; sacc[mh][nj][1] = p1;
                    sacc[mh][nj][2] = p2; sacc[mh][nj][3] = p3;
                    rs0 += p0 + p1; rs1 += p2 + p3;
                }
            } else {
                #pragma unroll
                for (int nj = 0; nj < 8; nj++) {
                    float p0 = ex2(sacc[mh][nj][0]);
                    float p1 = ex2(sacc[mh][nj][1]);
                    float p2 = ex2(sacc[mh][nj][2]);
                    float p3 = ex2(sacc[mh][nj][3]);
                    sacc[mh][nj][0] = p0; sacc[mh][nj][1] = p1;
                    sacc[mh][nj][2] = p2; sacc[mh][nj][3] = p3;
                    rs0 += p0 + p1; rs1 += p2 + p3;
                }
            }
            lm[mh][0] += rs0;
            lm[mh][1] += rs1;
        }

        // ---- O += P V ----
        #pragma unroll
        for (int s = 0; s < 4; s++) {
            unsigned vr[16];
            #pragma unroll
            for (int p = 0; p < 4; p++)
                ldm4t(vr[4*p], vr[4*p+1], vr[4*p+2], vr[4*p+3],
                      vb + (s*16*VH + p*16)*2);
            #pragma unroll
            for (int mh = 0; mh < 2; mh++) {
                unsigned a0 = pkh2(sacc[mh][2*s][0],   sacc[mh][2*s][1]);
                unsigned a1 = pkh2(sacc[mh][2*s][2],   sacc[mh][2*s][3]);
                unsigned a2 = pkh2(sacc[mh][2*s+1][0], sacc[mh][2*s+1][1]);
                unsigned a3 = pkh2(sacc[mh][2*s+1][2], sacc[mh][2*s+1][3]);
                #pragma unroll
                for (int p = 0; p < 4; p++) {
                    mma16(oacc[mh][2*p],   a0, a1, a2, a3, vr[4*p],   vr[4*p+1]);
                    mma16(oacc[mh][2*p+1], a0, a1, a2, a3, vr[4*p+2], vr[4*p+3]);
                }
            }
        }

        // stage kc+2 into ring slot (kc+2)%3: last read at chunk kc-1,
        // finished by all warps before this chunk's barrier.
        if (kc + 2 < nch) {
            ISSUE_KV(kc + 2, (kc + 2) % 3);
        }
    }
    #undef ISSUE_KV

    // ---- normalize and write out (B, S, H*D), float2 stores ----
    #pragma unroll
    for (int mh = 0; mh < 2; mh++) {
        float la = lm[mh][0], lb = lm[mh][1];
        la += __shfl_xor_sync(FULL, la, 1);
        la += __shfl_xor_sync(FULL, la, 2);
        lb += __shfl_xor_sync(FULL, lb, 1);
        lb += __shfl_xor_sync(FULL, lb, 2);
        float inv0 = 1.0f / la;
        float inv1 = 1.0f / lb;

        const int qa = q0 + wm + mh*16 + g;
        const int qb = qa + 8;
        #pragma unroll
        for (int dj = 0; dj < 8; dj++) {
            int d = h*HDIM + dj*8 + 2*t;
            float2 v0 = make_float2(oacc[mh][dj][0]*inv0, oacc[mh][dj][1]*inv0);
            float2 v1 = make_float2(oacc[mh][dj][2]*inv1, oacc[mh][dj][3]*inv1);
            *reinterpret_cast<float2*>(&out[(b*SEQ + qa)*EMB + d]) = v0;
            *reinterpret_cast<float2*>(&out[(b*SEQ + qb)*EMB + d]) = v1;
        }
    }
}

// ---------------------------------------------------------------------------
extern "C" void kernel_launch(void* const* d_in, const int* in_sizes, int n_in,
                              void* d_out, int out_size)
{
    const float* inp  = (const float*)d_in[0];
    const float* mask = (const float*)d_in[1];
    const float* Wq   = (const float*)d_in[2];
    const float* bq   = (const float*)d_in[3];
    const float* Wk   = (const float*)d_in[4];
    const float* bk   = (const float*)d_in[5];
    const float* Wv   = (const float*)d_in[6];
    const float* bv   = (const float*)d_in[7];
    float* out = (float*)d_out;

    cudaFuncSetAttribute(qkv_proj,
                         cudaFuncAttributeMaxDynamicSharedMemorySize,
                         (int)PROJ_SMEM);
    cudaFuncSetAttribute(attn_kernel,
                         cudaFuncAttributeMaxDynamicSharedMemorySize,
                         (int)ATTN_SMEM);

    setup_kernel<<<NB_SETUP, 256>>>(inp, mask, Wq, Wk, Wv);

    dim3 gproj(EMB/128, 64, 3);
    qkv_proj<<<gproj, 128, PROJ_SMEM>>>(bq, bk, bv);

    dim3 gattn(SEQ/128, HEADS, BATCH);
    attn_kernel<<<gattn, 128, ATTN_SMEM>>>(out);
}

// round 16
// speedup vs baseline: 1.0553x; 1.0395x over previous
#include <cuda_runtime.h>
#include <cuda_fp16.h>
#include <math.h>

#define BATCH 16
#define SEQ   512
#define EMB   768
#define HEADS 12
#define HDIM  64
#define ROWS  (BATCH*SEQ)          // 8192
#define BHN   (BATCH*HEADS)        // 192

// fp16 staging globals (natural layouts)
__device__ __half g_inph[ROWS*EMB];          // [m][k]
__device__ __half g_Wh[3*EMB*EMB];           // [w][k][n]
__device__ __half g_Qh[BHN*SEQ*HDIM];        // [bh][s][d], pre-scaled 0.125*log2(e)
__device__ __half g_Kh[BHN*SEQ*HDIM];        // [bh][j][d]  compacted keys
__device__ __half g_Vh[BHN*SEQ*HDIM];        // [bh][j][d]  compacted keys
__device__ int    g_srcs[BATCH*SEQ];         // compacted: global input row (b*512+s)
__device__ int    g_nk[BATCH];               // unmasked key count per batch

// ---------------------------------------------------------------------------
// helpers
// ---------------------------------------------------------------------------
__device__ __forceinline__ void mma16(float c[4],
                                      unsigned a0, unsigned a1, unsigned a2, unsigned a3,
                                      unsigned b0, unsigned b1) {
    asm volatile(
        "mma.sync.aligned.m16n8k16.row.col.f32.f16.f16.f32 "
        "{%0,%1,%2,%3}, {%4,%5,%6,%7}, {%8,%9}, {%0,%1,%2,%3};"
        : "+f"(c[0]), "+f"(c[1]), "+f"(c[2]), "+f"(c[3])
        : "r"(a0), "r"(a1), "r"(a2), "r"(a3), "r"(b0), "r"(b1));
}

__device__ __forceinline__ void ldm4(unsigned& r0, unsigned& r1,
                                     unsigned& r2, unsigned& r3, unsigned a) {
    asm volatile("ldmatrix.sync.aligned.m8n8.x4.shared.b16 {%0,%1,%2,%3}, [%4];"
                 : "=r"(r0), "=r"(r1), "=r"(r2), "=r"(r3) : "r"(a));
}
__device__ __forceinline__ void ldm4t(unsigned& r0, unsigned& r1,
                                      unsigned& r2, unsigned& r3, unsigned a) {
    asm volatile("ldmatrix.sync.aligned.m8n8.x4.trans.shared.b16 {%0,%1,%2,%3}, [%4];"
                 : "=r"(r0), "=r"(r1), "=r"(r2), "=r"(r3) : "r"(a));
}

__device__ __forceinline__ unsigned pkh2(float lo, float hi) {
    unsigned r;
    asm("cvt.rn.f16x2.f32 %0, %1, %2;" : "=r"(r) : "f"(hi), "f"(lo));
    return r;
}

__device__ __forceinline__ float ex2(float x) {
    float r;
    asm("ex2.approx.ftz.f32 %0, %1;" : "=f"(r) : "f"(x));
    return r;
}

__device__ __forceinline__ unsigned smem_u32(const void* p) {
    unsigned a;
    asm("{.reg .u64 t; cvta.to.shared.u64 t, %1; cvt.u32.u64 %0, t;}"
        : "=r"(a) : "l"(p));
    return a;
}

__device__ __forceinline__ void cpa16(unsigned dst, const void* src) {
    asm volatile("cp.async.ca.shared.global [%0], [%1], 16;" :: "r"(dst), "l"(src));
}
#define CP_COMMIT() asm volatile("cp.async.commit_group;" ::: "memory")
#define CP_WAIT(N)  asm volatile("cp.async.wait_group %0;" :: "n"(N) : "memory")

// ---------------------------------------------------------------------------
// merged setup kernel: compact (16) + cvt_w (432) + cvt_inp (1536), MLP=4
// ---------------------------------------------------------------------------
#define NB_CMP  16
#define NB_CVTW (3*144)            // EMB*EMB/4/1024 per matrix = 144
#define NB_CVTA 1536               // ROWS*EMB/4/1024
#define NB_SETUP (NB_CMP + NB_CVTW + NB_CVTA)

__global__ __launch_bounds__(256) void setup_kernel(
    const float* __restrict__ inp,  const float* __restrict__ mask,
    const float* __restrict__ Wq,   const float* __restrict__ Wk,
    const float* __restrict__ Wv)
{
    const int blk = blockIdx.x;
    const int tid = threadIdx.x;

    if (blk < NB_CMP) {
        const int b = blk;
        __shared__ int sc[512];
        int f0 = (mask[b*512 + tid]       == 0.0f) ? 1 : 0;
        int f1 = (mask[b*512 + 256 + tid] == 0.0f) ? 1 : 0;
        sc[tid] = f0; sc[tid + 256] = f1;
        __syncthreads();
        for (int off = 1; off < 512; off <<= 1) {
            int i0 = tid, i1 = tid + 256;
            int v0 = sc[i0] + ((i0 >= off) ? sc[i0 - off] : 0);
            int v1 = sc[i1] + ((i1 >= off) ? sc[i1 - off] : 0);
            __syncthreads();
            sc[i0] = v0; sc[i1] = v1;
            __syncthreads();
        }
        int nk = sc[511];
        if (f0) g_srcs[b*512 + sc[tid] - 1]       = b*512 + tid;
        if (f1) g_srcs[b*512 + sc[tid + 256] - 1] = b*512 + 256 + tid;
        if (tid >= nk)       g_srcs[b*512 + tid]       = b*512;
        if (tid + 256 >= nk) g_srcs[b*512 + 256 + tid] = b*512;
        if (tid == 0) g_nk[b] = nk;
    } else if (blk < NB_CMP + NB_CVTW) {
        const int rel = blk - NB_CMP;
        const int w = rel / 144;
        const float* W = (w == 0) ? Wq : (w == 1) ? Wk : Wv;
        const int base = (rel % 144) * 1024 + tid;     // float4 index
        float4 v[4];
        #pragma unroll
        for (int j = 0; j < 4; j++)
            v[j] = reinterpret_cast<const float4*>(W)[base + j*256];
        __half2* O = reinterpret_cast<__half2*>(g_Wh + (long)w*EMB*EMB);
        #pragma unroll
        for (int j = 0; j < 4; j++) {
            O[(base + j*256)*2]     = __floats2half2_rn(v[j].x, v[j].y);
            O[(base + j*256)*2 + 1] = __floats2half2_rn(v[j].z, v[j].w);
        }
    } else {
        const int base = (blk - NB_CMP - NB_CVTW) * 1024 + tid;  // float4 index
        float4 v[4];
        #pragma unroll
        for (int j = 0; j < 4; j++)
            v[j] = reinterpret_cast<const float4*>(inp)[base + j*256];
        __half2* O = reinterpret_cast<__half2*>(g_inph);
        #pragma unroll
        for (int j = 0; j < 4; j++) {
            O[(base + j*256)*2]     = __floats2half2_rn(v[j].x, v[j].y);
            O[(base + j*256)*2 + 1] = __floats2half2_rn(v[j].z, v[j].w);
        }
    }
}

// ---------------------------------------------------------------------------
// Kernel 1: fused QKV projection (exact R12 structure). 128 threads,
// 4 warps of 64x64. CTA tile 128x128, K-step 64 (12 iters), 2-buffer
// cp.async, MMA first then staging. 2 CTAs/SM.
// ---------------------------------------------------------------------------
#define AH    72
#define ABUFH (128*AH)             // 9216 halves
#define BHS   136
#define BBUFH (64*BHS)             // 8704 halves
#define PROJ_SMEM ((2*ABUFH + 2*BBUFH)*2)   // 71680 B

__global__ __launch_bounds__(128, 2) void qkv_proj(
    const float* __restrict__ bq, const float* __restrict__ bk,
    const float* __restrict__ bv)
{
    const int z = blockIdx.z;
    const int y = blockIdx.y;
    int bb = 0, tt = 0, nkb = 0;
    if (z > 0) {
        bb = y >> 2; tt = y & 3;
        nkb = g_nk[bb];
        if (tt*128 >= nkb) return;
    }

    const __half* Wp = g_Wh + (long)z*EMB*EMB;
    const float* bias = (z == 0) ? bq : (z == 1) ? bk : bv;

    const int n0 = blockIdx.x * 128;
    const int tid  = threadIdx.x;
    const int lane = tid & 31;
    const int wid  = tid >> 5;
    const int wm = (wid & 1) * 64;      // warp M offset (2 m-warps)
    const int wn = (wid >> 1) * 64;     // warp N offset (2 n-warps)
    const int g  = lane >> 2;
    const int t  = lane & 3;
    const int l15  = lane & 15;
    const int l7   = lane & 7;
    const int hi16 = (lane >> 4) & 1;
    const int hi8  = (lane >> 3) & 1;

    extern __shared__ __half sh[];
    const unsigned sb = smem_u32(sh);
    __shared__ int s_idx[128];

    if (tid < 128)
        s_idx[tid] = (z == 0) ? (y*128 + tid)
                              : g_srcs[bb*512 + tt*128 + tid];
    __syncthreads();

    const unsigned abase = sb + ((wm + l15)*AH + hi16*8)*2;
    const unsigned bbase = sb + 2*ABUFH*2 + ((l7 + hi8*8)*BHS + wn + hi16*8)*2;

    float acc[4][8][4];
    #pragma unroll
    for (int mi = 0; mi < 4; mi++)
        #pragma unroll
        for (int nj = 0; nj < 8; nj++)
            #pragma unroll
            for (int c = 0; c < 4; c++) acc[mi][nj][c] = 0.0f;

    #define ISSUE(IT, BUF) { \
        _Pragma("unroll") for (int i = 0; i < 8; i++) { \
            int f = tid + i*128; int r = f >> 3; int c8 = f & 7; \
            cpa16(sb + ((BUF)*ABUFH + r*AH + c8*8)*2, \
                  g_inph + (long)s_idx[r]*EMB + (IT)*64 + c8*8); } \
        _Pragma("unroll") for (int i = 0; i < 8; i++) { \
            int f = tid + i*128; int r = f >> 4; int c8 = f & 15; \
            cpa16(sb + (2*ABUFH + (BUF)*BBUFH + r*BHS + c8*8)*2, \
                  Wp + ((IT)*64 + r)*EMB + n0 + c8*8); } \
        CP_COMMIT(); }

    ISSUE(0, 0);
    ISSUE(1, 1);

    for (int it = 0; it < 12; it++) {
        if (it < 10) CP_WAIT(1); else CP_WAIT(0);
        __syncthreads();

        const int buf = it & 1;
        const unsigned ab = abase + buf*ABUFH*2;
        const unsigned bb2 = bbase + buf*BBUFH*2;

        #pragma unroll
        for (int s = 0; s < 4; s++) {
            unsigned a[4][4];
            #pragma unroll
            for (int mi = 0; mi < 4; mi++)
                ldm4(a[mi][0], a[mi][1], a[mi][2], a[mi][3],
                     ab + (mi*16*AH + s*16)*2);
            unsigned b[8][2];
            #pragma unroll
            for (int p = 0; p < 4; p++) {
                unsigned r0, r1, r2, r3;
                ldm4t(r0, r1, r2, r3, bb2 + (s*16*BHS + p*16)*2);
                b[2*p][0] = r0; b[2*p][1] = r1;
                b[2*p+1][0] = r2; b[2*p+1][1] = r3;
            }
            #pragma unroll
            for (int mi = 0; mi < 4; mi++)
                #pragma unroll
                for (int nj = 0; nj < 8; nj++)
                    mma16(acc[mi][nj], a[mi][0], a[mi][1], a[mi][2], a[mi][3],
                          b[nj][0], b[nj][1]);
        }

        if (it + 2 < 12) {
            __syncthreads();
            ISSUE(it + 2, buf);
        }
    }
    #undef ISSUE

    // Epilogue: half2 stores (n even, pairs within one head).
    if (z == 0) {
        const float qs = 0.18033688f;   // 0.125 * log2(e)
        #pragma unroll
        for (int mi = 0; mi < 4; mi++) {
            #pragma unroll
            for (int nj = 0; nj < 8; nj++) {
                int n = n0 + wn + nj*8 + 2*t;
                int h = n >> 6, d = n & 63;
                float b0v = bias[n], b1v = bias[n+1];
                int row = y*128 + wm + mi*16 + g;
                int b = row >> 9, s = row & 511;
                __half2* p0 = reinterpret_cast<__half2*>(
                    &g_Qh[((long)(b*HEADS + h)*SEQ + s)*HDIM + d]);
                *p0 = __floats2half2_rn((acc[mi][nj][0] + b0v)*qs,
                                        (acc[mi][nj][1] + b1v)*qs);
                int row2 = row + 8;
                int b2 = row2 >> 9, s2 = row2 & 511;
                __half2* p1 = reinterpret_cast<__half2*>(
                    &g_Qh[((long)(b2*HEADS + h)*SEQ + s2)*HDIM + d]);
                *p1 = __floats2half2_rn((acc[mi][nj][2] + b0v)*qs,
                                        (acc[mi][nj][3] + b1v)*qs);
            }
        }
    } else {
        __half* outh = (z == 1) ? g_Kh : g_Vh;
        #pragma unroll
        for (int mi = 0; mi < 4; mi++) {
            #pragma unroll
            for (int nj = 0; nj < 8; nj++) {
                int n = n0 + wn + nj*8 + 2*t;
                int h = n >> 6, d = n & 63;
                float b0v = bias[n], b1v = bias[n+1];
                int j0 = tt*128 + wm + mi*16 + g;
                if (j0 < nkb) {
                    __half2* p0 = reinterpret_cast<__half2*>(
                        &outh[((long)(bb*HEADS + h)*SEQ + j0)*HDIM + d]);
                    *p0 = __floats2half2_rn(acc[mi][nj][0] + b0v,
                                            acc[mi][nj][1] + b1v);
                }
                int j1 = j0 + 8;
                if (j1 < nkb) {
                    __half2* p1 = reinterpret_cast<__half2*>(
                        &outh[((long)(bb*HEADS + h)*SEQ + j1)*HDIM + d]);
                    *p1 = __floats2half2_rn(acc[mi][nj][2] + b0v,
                                            acc[mi][nj][3] + b1v);
                }
            }
        }
    }
}

// ---------------------------------------------------------------------------
// Kernel 2: flash attention over COMPACTED keys (R12 structure) with Q
// fragments hoisted into registers (loaded once, reused every chunk).
// 128 threads, 4 warps x 32 query rows. 2 CTAs/SM.
// ---------------------------------------------------------------------------
#define QH    72
#define QBUFH (128*QH)             // 9216
#define KH    72
#define KBUFH (64*KH)              // 4608
#define VH    72
#define VBUFH (64*VH)              // 4608
#define ATTN_SMEM ((QBUFH + 2*KBUFH + 2*VBUFH)*2)   // 55296 B

__global__ __launch_bounds__(128, 2) void attn_kernel(float* __restrict__ out)
{
    const int b  = blockIdx.z;
    const int h  = blockIdx.y;
    const int bh = b*HEADS + h;
    const int q0 = blockIdx.x * 128;
    const int tid  = threadIdx.x;
    const int lane = tid & 31;
    const int wid  = tid >> 5;
    const int wm = wid * 32;           // warp covers 32 query rows
    const int g  = lane >> 2;
    const int t  = lane & 3;
    const int l15  = lane & 15;
    const int l7   = lane & 7;
    const int hi16 = (lane >> 4) & 1;
    const int hi8  = (lane >> 3) & 1;

    const int nk  = g_nk[b];
    const int nch = (nk + 63) >> 6;

    extern __shared__ __half sh[];
    const unsigned sb = smem_u32(sh);

    const __half* Qg = g_Qh + (long)bh*SEQ*HDIM + (long)q0*HDIM;
    const __half* Kg = g_Kh + (long)bh*SEQ*HDIM;
    const __half* Vg = g_Vh + (long)bh*SEQ*HDIM;

    const unsigned qbase = sb + ((wm + l15)*QH + hi16*8)*2;
    const unsigned kbase = sb + QBUFH*2 + ((l7 + hi16*8)*KH + hi8*8)*2;
    const unsigned vbase = sb + (QBUFH + 2*KBUFH)*2 + ((l7 + hi8*8)*VH + hi16*8)*2;

    #define ISSUE_KV(KC, BUF) { \
        _Pragma("unroll") for (int i = 0; i < 4; i++) { \
            int f = tid + i*128; int r = f >> 3; int c8 = f & 7; \
            cpa16(sb + (QBUFH + (BUF)*KBUFH + r*KH + c8*8)*2, \
                  Kg + ((KC)*64 + r)*HDIM + c8*8); } \
        _Pragma("unroll") for (int i = 0; i < 4; i++) { \
            int f = tid + i*128; int r = f >> 3; int c8 = f & 7; \
            cpa16(sb + (QBUFH + 2*KBUFH + (BUF)*VBUFH + r*VH + c8*8)*2, \
                  Vg + ((KC)*64 + r)*HDIM + c8*8); } \
        CP_COMMIT(); }

    // Prologue: Q + chunk0 (group 0), chunk1 (group 1).
    {
        #pragma unroll
        for (int i = 0; i < 8; i++) {
            int f = tid + i*128; int r = f >> 3; int c8 = f & 7;
            cpa16(sb + (r*QH + c8*8)*2, Qg + r*HDIM + c8*8);
        }
        ISSUE_KV(0, 0);
        ISSUE_KV(1, 1);
    }

    // Hoist Q fragments into registers (group 0 contains Q + K0 + V0).
    unsigned qf[2][4][4];
    CP_WAIT(1);
    __syncthreads();
    #pragma unroll
    for (int mh = 0; mh < 2; mh++)
        #pragma unroll
        for (int s = 0; s < 4; s++)
            ldm4(qf[mh][s][0], qf[mh][s][1], qf[mh][s][2], qf[mh][s][3],
                 qbase + (mh*16*QH + s*16)*2);

    float oacc[2][8][4];
    #pragma unroll
    for (int mh = 0; mh < 2; mh++)
        #pragma unroll
        for (int dj = 0; dj < 8; dj++)
            #pragma unroll
            for (int c = 0; c < 4; c++) oacc[mh][dj][c] = 0.0f;
    float lm[2][2] = {{0.0f, 0.0f}, {0.0f, 0.0f}};
    const unsigned FULL = 0xffffffffu;

    for (int kc = 0; kc < nch; kc++) {
        if (kc + 2 < nch) CP_WAIT(1); else CP_WAIT(0);
        __syncthreads();

        const int buf = kc & 1;
        const unsigned kb = kbase + buf*KBUFH*2;
        const unsigned vb = vbase + buf*VBUFH*2;

        // ---- S' = Q K^T (Q pre-scaled by 0.125*log2e) ----
        float sacc[2][8][4];
        #pragma unroll
        for (int mh = 0; mh < 2; mh++)
            #pragma unroll
            for (int nj = 0; nj < 8; nj++)
                #pragma unroll
                for (int c = 0; c < 4; c++) sacc[mh][nj][c] = 0.0f;

        #pragma unroll
        for (int s = 0; s < 4; s++) {
            unsigned kr[16];
            #pragma unroll
            for (int p = 0; p < 4; p++)
                ldm4(kr[4*p], kr[4*p+1], kr[4*p+2], kr[4*p+3],
                     kb + (p*16*KH + s*16)*2);
            #pragma unroll
            for (int mh = 0; mh < 2; mh++) {
                #pragma unroll
                for (int p = 0; p < 4; p++) {
                    mma16(sacc[mh][2*p],   qf[mh][s][0], qf[mh][s][1],
                          qf[mh][s][2], qf[mh][s][3], kr[4*p],   kr[4*p+1]);
                    mma16(sacc[mh][2*p+1], qf[mh][s][0], qf[mh][s][1],
                          qf[mh][s][2], qf[mh][s][3], kr[4*p+2], kr[4*p+3]);
                }
            }
        }

        // ---- P = exp2(S'); tail chunk zeroes padded keys ----
        #pragma unroll
        for (int mh = 0; mh < 2; mh++) {
            float rs0 = 0.0f, rs1 = 0.0f;
            if (kc + 1 == nch) {
                #pragma unroll
                for (int nj = 0; nj < 8; nj++) {
                    int key = kc*64 + nj*8 + 2*t;
                    float p0 = (key   < nk) ? ex2(sacc[mh][nj][0]) : 0.0f;
                    float p1 = (key+1 < nk) ? ex2(sacc[mh][nj][1]) : 0.0f;
                    float p2 = (key   < nk) ? ex2(sacc[mh][nj][2]) : 0.0f;
                    float p3 = (key+1 < nk) ? ex2(sacc[mh][nj][3]) : 0.0f;
                    sacc[mh][nj][0] = p0; sacc[mh][nj][1] = p1;
                    sacc[mh][nj][2] = p2; sacc[mh][nj][3] = p3;
                    rs0 += p0 + p1; rs1 += p2 + p3;
                }
            } else {
                #pragma unroll
                for (int nj = 0; nj < 8; nj++) {
                    float p0 = ex2(sacc[mh][nj][0]);
                    float p1 = ex2(sacc[mh][nj][1]);
                    float p2 = ex2(sacc[mh][nj][2]);
                    float p3 = ex2(sacc[mh][nj][3]);
                    sacc[mh][nj][0] = p0; sacc[mh][nj][1] = p1;
                    sacc[mh][nj][2] = p2; sacc[mh][nj][3] = p3;
                    rs0 += p0 + p1; rs1 += p2 + p3;
                }
            }
            lm[mh][0] += rs0;
            lm[mh][1] += rs1;
        }

        // ---- O += P V ----
        #pragma unroll
        for (int s = 0; s < 4; s++) {
            unsigned vr[16];
            #pragma unroll
            for (int p = 0; p < 4; p++)
                ldm4t(vr[4*p], vr[4*p+1], vr[4*p+2], vr[4*p+3],
                      vb + (s*16*VH + p*16)*2);
            #pragma unroll
            for (int mh = 0; mh < 2; mh++) {
                unsigned a0 = pkh2(sacc[mh][2*s][0],   sacc[mh][2*s][1]);
                unsigned a1 = pkh2(sacc[mh][2*s][2],   sacc[mh][2*s][3]);
                unsigned a2 = pkh2(sacc[mh][2*s+1][0], sacc[mh][2*s+1][1]);
                unsigned a3 = pkh2(sacc[mh][2*s+1][2], sacc[mh][2*s+1][3]);
                #pragma unroll
                for (int p = 0; p < 4; p++) {
                    mma16(oacc[mh][2*p],   a0, a1, a2, a3, vr[4*p],   vr[4*p+1]);
                    mma16(oacc[mh][2*p+1], a0, a1, a2, a3, vr[4*p+2], vr[4*p+3]);
                }
            }
        }

        if (kc + 2 < nch) {
            __syncthreads();
            ISSUE_KV(kc + 2, buf);
        }
    }
    #undef ISSUE_KV

    // ---- normalize and write out (B, S, H*D), float2 stores ----
    #pragma unroll
    for (int mh = 0; mh < 2; mh++) {
        float la = lm[mh][0], lb = lm[mh][1];
        la += __shfl_xor_sync(FULL, la, 1);
        la += __shfl_xor_sync(FULL, la, 2);
        lb += __shfl_xor_sync(FULL, lb, 1);
        lb += __shfl_xor_sync(FULL, lb, 2);
        float inv0 = 1.0f / la;
        float inv1 = 1.0f / lb;

        const int qa = q0 + wm + mh*16 + g;
        const int qb = qa + 8;
        #pragma unroll
        for (int dj = 0; dj < 8; dj++) {
            int d = h*HDIM + dj*8 + 2*t;
            float2 v0 = make_float2(oacc[mh][dj][0]*inv0, oacc[mh][dj][1]*inv0);
            float2 v1 = make_float2(oacc[mh][dj][2]*inv1, oacc[mh][dj][3]*inv1);
            *reinterpret_cast<float2*>(&out[(b*SEQ + qa)*EMB + d]) = v0;
            *reinterpret_cast<float2*>(&out[(b*SEQ + qb)*EMB + d]) = v1;
        }
    }
}

// ---------------------------------------------------------------------------
extern "C" void kernel_launch(void* const* d_in, const int* in_sizes, int n_in,
                              void* d_out, int out_size)
{
    const float* inp  = (const float*)d_in[0];
    const float* mask = (const float*)d_in[1];
    const float* Wq   = (const float*)d_in[2];
    const float* bq   = (const float*)d_in[3];
    const float* Wk   = (const float*)d_in[4];
    const float* bk   = (const float*)d_in[5];
    const float* Wv   = (const float*)d_in[6];
    const float* bv   = (const float*)d_in[7];
    float* out = (float*)d_out;

    cudaFuncSetAttribute(qkv_proj,
                         cudaFuncAttributeMaxDynamicSharedMemorySize,
                         (int)PROJ_SMEM);
    cudaFuncSetAttribute(attn_kernel,
                         cudaFuncAttributeMaxDynamicSharedMemorySize,
                         (int)ATTN_SMEM);

    setup_kernel<<<NB_SETUP, 256>>>(inp, mask, Wq, Wk, Wv);

    dim3 gproj(EMB/128, 64, 3);
    qkv_proj<<<gproj, 128, PROJ_SMEM>>>(bq, bk, bv);

    dim3 gattn(SEQ/128, HEADS, BATCH);
    attn_kernel<<<gattn, 128, ATTN_SMEM>>>(out);
}

// round 17
// speedup vs baseline: 1.0991x; 1.0415x over previous
#include <cuda_runtime.h>
#include <cuda_fp16.h>
#include <math.h>

#define BATCH 16
#define SEQ   512
#define EMB   768
#define HEADS 12
#define HDIM  64
#define ROWS  (BATCH*SEQ)          // 8192
#define BHN   (BATCH*HEADS)        // 192

// fp16 staging globals (natural layouts)
__device__ __half g_inph[ROWS*EMB];          // [m][k]
__device__ __half g_Wh[3*EMB*EMB];           // [w][k][n]
__device__ __half g_Qh[BHN*SEQ*HDIM];        // [bh][s][d], pre-scaled 0.125*log2(e)
__device__ __half g_Kh[BHN*SEQ*HDIM];        // [bh][j][d]  compacted keys
__device__ __half g_Vh[BHN*SEQ*HDIM];        // [bh][j][d]  compacted keys
__device__ int    g_srcs[BATCH*SEQ];         // compacted: global input row (b*512+s)
__device__ int    g_nk[BATCH];               // unmasked key count per batch

// ---------------------------------------------------------------------------
// helpers
// ---------------------------------------------------------------------------
__device__ __forceinline__ void mma16(float c[4],
                                      unsigned a0, unsigned a1, unsigned a2, unsigned a3,
                                      unsigned b0, unsigned b1) {
    asm volatile(
        "mma.sync.aligned.m16n8k16.row.col.f32.f16.f16.f32 "
        "{%0,%1,%2,%3}, {%4,%5,%6,%7}, {%8,%9}, {%0,%1,%2,%3};"
        : "+f"(c[0]), "+f"(c[1]), "+f"(c[2]), "+f"(c[3])
        : "r"(a0), "r"(a1), "r"(a2), "r"(a3), "r"(b0), "r"(b1));
}

__device__ __forceinline__ void ldm4(unsigned& r0, unsigned& r1,
                                     unsigned& r2, unsigned& r3, unsigned a) {
    asm volatile("ldmatrix.sync.aligned.m8n8.x4.shared.b16 {%0,%1,%2,%3}, [%4];"
                 : "=r"(r0), "=r"(r1), "=r"(r2), "=r"(r3) : "r"(a));
}
__device__ __forceinline__ void ldm4t(unsigned& r0, unsigned& r1,
                                      unsigned& r2, unsigned& r3, unsigned a) {
    asm volatile("ldmatrix.sync.aligned.m8n8.x4.trans.shared.b16 {%0,%1,%2,%3}, [%4];"
                 : "=r"(r0), "=r"(r1), "=r"(r2), "=r"(r3) : "r"(a));
}

__device__ __forceinline__ unsigned pkh2(float lo, float hi) {
    unsigned r;
    asm("cvt.rn.f16x2.f32 %0, %1, %2;" : "=r"(r) : "f"(hi), "f"(lo));
    return r;
}

__device__ __forceinline__ float ex2(float x) {
    float r;
    asm("ex2.approx.ftz.f32 %0, %1;" : "=f"(r) : "f"(x));
    return r;
}

__device__ __forceinline__ unsigned smem_u32(const void* p) {
    unsigned a;
    asm("{.reg .u64 t; cvta.to.shared.u64 t, %1; cvt.u32.u64 %0, t;}"
        : "=r"(a) : "l"(p));
    return a;
}

// L2-only staging: data is consumed once via ldmatrix; keep it out of L1.
__device__ __forceinline__ void cpa16(unsigned dst, const void* src) {
    asm volatile("cp.async.cg.shared.global [%0], [%1], 16;" :: "r"(dst), "l"(src));
}
#define CP_COMMIT() asm volatile("cp.async.commit_group;" ::: "memory")
#define CP_WAIT(N)  asm volatile("cp.async.wait_group %0;" :: "n"(N) : "memory")

// ---------------------------------------------------------------------------
// merged setup kernel: compact (16) + cvt_w (432) + cvt_inp (1536), MLP=4
// ---------------------------------------------------------------------------
#define NB_CMP  16
#define NB_CVTW (3*144)            // EMB*EMB/4/1024 per matrix = 144
#define NB_CVTA 1536               // ROWS*EMB/4/1024
#define NB_SETUP (NB_CMP + NB_CVTW + NB_CVTA)

__global__ __launch_bounds__(256) void setup_kernel(
    const float* __restrict__ inp,  const float* __restrict__ mask,
    const float* __restrict__ Wq,   const float* __restrict__ Wk,
    const float* __restrict__ Wv)
{
    const int blk = blockIdx.x;
    const int tid = threadIdx.x;

    if (blk < NB_CMP) {
        const int b = blk;
        __shared__ int sc[512];
        int f0 = (mask[b*512 + tid]       == 0.0f) ? 1 : 0;
        int f1 = (mask[b*512 + 256 + tid] == 0.0f) ? 1 : 0;
        sc[tid] = f0; sc[tid + 256] = f1;
        __syncthreads();
        for (int off = 1; off < 512; off <<= 1) {
            int i0 = tid, i1 = tid + 256;
            int v0 = sc[i0] + ((i0 >= off) ? sc[i0 - off] : 0);
            int v1 = sc[i1] + ((i1 >= off) ? sc[i1 - off] : 0);
            __syncthreads();
            sc[i0] = v0; sc[i1] = v1;
            __syncthreads();
        }
        int nk = sc[511];
        if (f0) g_srcs[b*512 + sc[tid] - 1]       = b*512 + tid;
        if (f1) g_srcs[b*512 + sc[tid + 256] - 1] = b*512 + 256 + tid;
        if (tid >= nk)       g_srcs[b*512 + tid]       = b*512;
        if (tid + 256 >= nk) g_srcs[b*512 + 256 + tid] = b*512;
        if (tid == 0) g_nk[b] = nk;
    } else if (blk < NB_CMP + NB_CVTW) {
        const int rel = blk - NB_CMP;
        const int w = rel / 144;
        const float* W = (w == 0) ? Wq : (w == 1) ? Wk : Wv;
        const int base = (rel % 144) * 1024 + tid;     // float4 index
        float4 v[4];
        #pragma unroll
        for (int j = 0; j < 4; j++)
            v[j] = reinterpret_cast<const float4*>(W)[base + j*256];
        __half2* O = reinterpret_cast<__half2*>(g_Wh + (long)w*EMB*EMB);
        #pragma unroll
        for (int j = 0; j < 4; j++) {
            O[(base + j*256)*2]     = __floats2half2_rn(v[j].x, v[j].y);
            O[(base + j*256)*2 + 1] = __floats2half2_rn(v[j].z, v[j].w);
        }
    } else {
        const int base = (blk - NB_CMP - NB_CVTW) * 1024 + tid;  // float4 index
        float4 v[4];
        #pragma unroll
        for (int j = 0; j < 4; j++)
            v[j] = reinterpret_cast<const float4*>(inp)[base + j*256];
        __half2* O = reinterpret_cast<__half2*>(g_inph);
        #pragma unroll
        for (int j = 0; j < 4; j++) {
            O[(base + j*256)*2]     = __floats2half2_rn(v[j].x, v[j].y);
            O[(base + j*256)*2 + 1] = __floats2half2_rn(v[j].z, v[j].w);
        }
    }
}

// ---------------------------------------------------------------------------
// Kernel 1: fused QKV projection (R12 structure). 128 threads,
// 4 warps of 64x64. CTA tile 128x128, K-step 64 (12 iters), 2-buffer
// cp.async, MMA first then staging. 2 CTAs/SM.
// ---------------------------------------------------------------------------
#define AH    72
#define ABUFH (128*AH)             // 9216 halves
#define BHS   136
#define BBUFH (64*BHS)             // 8704 halves
#define PROJ_SMEM ((2*ABUFH + 2*BBUFH)*2)   // 71680 B

__global__ __launch_bounds__(128, 2) void qkv_proj(
    const float* __restrict__ bq, const float* __restrict__ bk,
    const float* __restrict__ bv)
{
    const int z = blockIdx.z;
    const int y = blockIdx.y;
    int bb = 0, tt = 0, nkb = 0;
    if (z > 0) {
        bb = y >> 2; tt = y & 3;
        nkb = g_nk[bb];
        if (tt*128 >= nkb) return;
    }

    const __half* Wp = g_Wh + (long)z*EMB*EMB;
    const float* bias = (z == 0) ? bq : (z == 1) ? bk : bv;

    const int n0 = blockIdx.x * 128;
    const int tid  = threadIdx.x;
    const int lane = tid & 31;
    const int wid  = tid >> 5;
    const int wm = (wid & 1) * 64;      // warp M offset (2 m-warps)
    const int wn = (wid >> 1) * 64;     // warp N offset (2 n-warps)
    const int g  = lane >> 2;
    const int t  = lane & 3;
    const int l15  = lane & 15;
    const int l7   = lane & 7;
    const int hi16 = (lane >> 4) & 1;
    const int hi8  = (lane >> 3) & 1;

    extern __shared__ __half sh[];
    const unsigned sb = smem_u32(sh);
    __shared__ int s_idx[128];

    if (tid < 128)
        s_idx[tid] = (z == 0) ? (y*128 + tid)
                              : g_srcs[bb*512 + tt*128 + tid];
    __syncthreads();

    const unsigned abase = sb + ((wm + l15)*AH + hi16*8)*2;
    const unsigned bbase = sb + 2*ABUFH*2 + ((l7 + hi8*8)*BHS + wn + hi16*8)*2;

    float acc[4][8][4];
    #pragma unroll
    for (int mi = 0; mi < 4; mi++)
        #pragma unroll
        for (int nj = 0; nj < 8; nj++)
            #pragma unroll
            for (int c = 0; c < 4; c++) acc[mi][nj][c] = 0.0f;

    #define ISSUE(IT, BUF) { \
        _Pragma("unroll") for (int i = 0; i < 8; i++) { \
            int f = tid + i*128; int r = f >> 3; int c8 = f & 7; \
            cpa16(sb + ((BUF)*ABUFH + r*AH + c8*8)*2, \
                  g_inph + (long)s_idx[r]*EMB + (IT)*64 + c8*8); } \
        _Pragma("unroll") for (int i = 0; i < 8; i++) { \
            int f = tid + i*128; int r = f >> 4; int c8 = f & 15; \
            cpa16(sb + (2*ABUFH + (BUF)*BBUFH + r*BHS + c8*8)*2, \
                  Wp + ((IT)*64 + r)*EMB + n0 + c8*8); } \
        CP_COMMIT(); }

    ISSUE(0, 0);
    ISSUE(1, 1);

    for (int it = 0; it < 12; it++) {
        if (it < 10) CP_WAIT(1); else CP_WAIT(0);
        __syncthreads();

        const int buf = it & 1;
        const unsigned ab = abase + buf*ABUFH*2;
        const unsigned bb2 = bbase + buf*BBUFH*2;

        #pragma unroll
        for (int s = 0; s < 4; s++) {
            unsigned a[4][4];
            #pragma unroll
            for (int mi = 0; mi < 4; mi++)
                ldm4(a[mi][0], a[mi][1], a[mi][2], a[mi][3],
                     ab + (mi*16*AH + s*16)*2);
            unsigned b[8][2];
            #pragma unroll
            for (int p = 0; p < 4; p++) {
                unsigned r0, r1, r2, r3;
                ldm4t(r0, r1, r2, r3, bb2 + (s*16*BHS + p*16)*2);
                b[2*p][0] = r0; b[2*p][1] = r1;
                b[2*p+1][0] = r2; b[2*p+1][1] = r3;
            }
            #pragma unroll
            for (int mi = 0; mi < 4; mi++)
                #pragma unroll
                for (int nj = 0; nj < 8; nj++)
                    mma16(acc[mi][nj], a[mi][0], a[mi][1], a[mi][2], a[mi][3],
                          b[nj][0], b[nj][1]);
        }

        if (it + 2 < 12) {
            __syncthreads();
            ISSUE(it + 2, buf);
        }
    }
    #undef ISSUE

    // Epilogue: half2 stores (n even, pairs within one head).
    if (z == 0) {
        const float qs = 0.18033688f;   // 0.125 * log2(e)
        #pragma unroll
        for (int mi = 0; mi < 4; mi++) {
            #pragma unroll
            for (int nj = 0; nj < 8; nj++) {
                int n = n0 + wn + nj*8 + 2*t;
                int h = n >> 6, d = n & 63;
                float b0v = bias[n], b1v = bias[n+1];
                int row = y*128 + wm + mi*16 + g;
                int b = row >> 9, s = row & 511;
                __half2* p0 = reinterpret_cast<__half2*>(
                    &g_Qh[((long)(b*HEADS + h)*SEQ + s)*HDIM + d]);
                *p0 = __floats2half2_rn((acc[mi][nj][0] + b0v)*qs,
                                        (acc[mi][nj][1] + b1v)*qs);
                int row2 = row + 8;
                int b2 = row2 >> 9, s2 = row2 & 511;
                __half2* p1 = reinterpret_cast<__half2*>(
                    &g_Qh[((long)(b2*HEADS + h)*SEQ + s2)*HDIM + d]);
                *p1 = __floats2half2_rn((acc[mi][nj][2] + b0v)*qs,
                                        (acc[mi][nj][3] + b1v)*qs);
            }
        }
    } else {
        __half* outh = (z == 1) ? g_Kh : g_Vh;
        #pragma unroll
        for (int mi = 0; mi < 4; mi++) {
            #pragma unroll
            for (int nj = 0; nj < 8; nj++) {
                int n = n0 + wn + nj*8 + 2*t;
                int h = n >> 6, d = n & 63;
                float b0v = bias[n], b1v = bias[n+1];
                int j0 = tt*128 + wm + mi*16 + g;
                if (j0 < nkb) {
                    __half2* p0 = reinterpret_cast<__half2*>(
                        &outh[((long)(bb*HEADS + h)*SEQ + j0)*HDIM + d]);
                    *p0 = __floats2half2_rn(acc[mi][nj][0] + b0v,
                                            acc[mi][nj][1] + b1v);
                }
                int j1 = j0 + 8;
                if (j1 < nkb) {
                    __half2* p1 = reinterpret_cast<__half2*>(
                        &outh[((long)(bb*HEADS + h)*SEQ + j1)*HDIM + d]);
                    *p1 = __floats2half2_rn(acc[mi][nj][2] + b0v,
                                            acc[mi][nj][3] + b1v);
                }
            }
        }
    }
}

// ---------------------------------------------------------------------------
// Kernel 2: flash attention over COMPACTED keys (R12 structure) with Q
// fragments hoisted into registers. 128 threads, 4 warps x 32 query rows.
// 2 CTAs/SM.
// ---------------------------------------------------------------------------
#define QH    72
#define QBUFH (128*QH)             // 9216
#define KH    72
#define KBUFH (64*KH)              // 4608
#define VH    72
#define VBUFH (64*VH)              // 4608
#define ATTN_SMEM ((QBUFH + 2*KBUFH + 2*VBUFH)*2)   // 55296 B

__global__ __launch_bounds__(128, 2) void attn_kernel(float* __restrict__ out)
{
    const int b  = blockIdx.z;
    const int h  = blockIdx.y;
    const int bh = b*HEADS + h;
    const int q0 = blockIdx.x * 128;
    const int tid  = threadIdx.x;
    const int lane = tid & 31;
    const int wid  = tid >> 5;
    const int wm = wid * 32;           // warp covers 32 query rows
    const int g  = lane >> 2;
    const int t  = lane & 3;
    const int l15  = lane & 15;
    const int l7   = lane & 7;
    const int hi16 = (lane >> 4) & 1;
    const int hi8  = (lane >> 3) & 1;

    const int nk  = g_nk[b];
    const int nch = (nk + 63) >> 6;

    extern __shared__ __half sh[];
    const unsigned sb = smem_u32(sh);

    const __half* Qg = g_Qh + (long)bh*SEQ*HDIM + (long)q0*HDIM;
    const __half* Kg = g_Kh + (long)bh*SEQ*HDIM;
    const __half* Vg = g_Vh + (long)bh*SEQ*HDIM;

    const unsigned qbase = sb + ((wm + l15)*QH + hi16*8)*2;
    const unsigned kbase = sb + QBUFH*2 + ((l7 + hi16*8)*KH + hi8*8)*2;
    const unsigned vbase = sb + (QBUFH + 2*KBUFH)*2 + ((l7 + hi8*8)*VH + hi16*8)*2;

    #define ISSUE_KV(KC, BUF) { \
        _Pragma("unroll") for (int i = 0; i < 4; i++) { \
            int f = tid + i*128; int r = f >> 3; int c8 = f & 7; \
            cpa16(sb + (QBUFH + (BUF)*KBUFH + r*KH + c8*8)*2, \
                  Kg + ((KC)*64 + r)*HDIM + c8*8); } \
        _Pragma("unroll") for (int i = 0; i < 4; i++) { \
            int f = tid + i*128; int r = f >> 3; int c8 = f & 7; \
            cpa16(sb + (QBUFH + 2*KBUFH + (BUF)*VBUFH + r*VH + c8*8)*2, \
                  Vg + ((KC)*64 + r)*HDIM + c8*8); } \
        CP_COMMIT(); }

    // Prologue: Q + chunk0 (group 0), chunk1 (group 1).
    {
        #pragma unroll
        for (int i = 0; i < 8; i++) {
            int f = tid + i*128; int r = f >> 3; int c8 = f & 7;
            cpa16(sb + (r*QH + c8*8)*2, Qg + r*HDIM + c8*8);
        }
        ISSUE_KV(0, 0);
        ISSUE_KV(1, 1);
    }

    // Hoist Q fragments into registers (group 0 contains Q + K0 + V0).
    unsigned qf[2][4][4];
    CP_WAIT(1);
    __syncthreads();
    #pragma unroll
    for (int mh = 0; mh < 2; mh++)
        #pragma unroll
        for (int s = 0; s < 4; s++)
            ldm4(qf[mh][s][0], qf[mh][s][1], qf[mh][s][2], qf[mh][s][3],
                 qbase + (mh*16*QH + s*16)*2);

    float oacc[2][8][4];
    #pragma unroll
    for (int mh = 0; mh < 2; mh++)
        #pragma unroll
        for (int dj = 0; dj < 8; dj++)
            #pragma unroll
            for (int c = 0; c < 4; c++) oacc[mh][dj][c] = 0.0f;
    float lm[2][2] = {{0.0f, 0.0f}, {0.0f, 0.0f}};
    const unsigned FULL = 0xffffffffu;

    for (int kc = 0; kc < nch; kc++) {
        if (kc + 2 < nch) CP_WAIT(1); else CP_WAIT(0);
        __syncthreads();

        const int buf = kc & 1;
        const unsigned kb = kbase + buf*KBUFH*2;
        const unsigned vb = vbase + buf*VBUFH*2;

        // ---- S' = Q K^T (Q pre-scaled by 0.125*log2e) ----
        float sacc[2][8][4];
        #pragma unroll
        for (int mh = 0; mh < 2; mh++)
            #pragma unroll
            for (int nj = 0; nj < 8; nj++)
                #pragma unroll
                for (int c = 0; c < 4; c++) sacc[mh][nj][c] = 0.0f;

        #pragma unroll
        for (int s = 0; s < 4; s++) {
            unsigned kr[16];
            #pragma unroll
            for (int p = 0; p < 4; p++)
                ldm4(kr[4*p], kr[4*p+1], kr[4*p+2], kr[4*p+3],
                     kb + (p*16*KH + s*16)*2);
            #pragma unroll
            for (int mh = 0; mh < 2; mh++) {
                #pragma unroll
                for (int p = 0; p < 4; p++) {
                    mma16(sacc[mh][2*p],   qf[mh][s][0], qf[mh][s][1],
                          qf[mh][s][2], qf[mh][s][3], kr[4*p],   kr[4*p+1]);
                    mma16(sacc[mh][2*p+1], qf[mh][s][0], qf[mh][s][1],
                          qf[mh][s][2], qf[mh][s][3], kr[4*p+2], kr[4*p+3]);
                }
            }
        }

        // ---- P = exp2(S'); tail chunk zeroes padded keys ----
        #pragma unroll
        for (int mh = 0; mh < 2; mh++) {
            float rs0 = 0.0f, rs1 = 0.0f;
            if (kc + 1 == nch) {
                #pragma unroll
                for (int nj = 0; nj < 8; nj++) {
                    int key = kc*64 + nj*8 + 2*t;
                    float p0 = (key   < nk) ? ex2(sacc[mh][nj][0]) : 0.0f;
                    float p1 = (key+1 < nk) ? ex2(sacc[mh][nj][1]) : 0.0f;
                    float p2 = (key   < nk) ? ex2(sacc[mh][nj][2]) : 0.0f;
                    float p3 = (key+1 < nk) ? ex2(sacc[mh][nj][3]) : 0.0f;
                    sacc[mh][nj][0] = p0; sacc[mh][nj][1] = p1;
                    sacc[mh][nj][2] = p2; sacc[mh][nj][3] = p3;
                    rs0 += p0 + p1; rs1 += p2 + p3;
                }
            } else {
                #pragma unroll
                for (int nj = 0; nj < 8; nj++) {
                    float p0 = ex2(sacc[mh][nj][0]);
                    float p1 = ex2(sacc[mh][nj][1]);
                    float p2 = ex2(sacc[mh][nj][2]);
                    float p3 = ex2(sacc[mh][nj][3]);
                    sacc[mh][nj][0] = p0; sacc[mh][nj][1] = p1;
                    sacc[mh][nj][2] = p2; sacc[mh][nj][3] = p3;
                    rs0 += p0 + p1; rs1 += p2 + p3;
                }
            }
            lm[mh][0] += rs0;
            lm[mh][1] += rs1;
        }

        // ---- O += P V ----
        #pragma unroll
        for (int s = 0; s < 4; s++) {
            unsigned vr[16];
            #pragma unroll
            for (int p = 0; p < 4; p++)
                ldm4t(vr[4*p], vr[4*p+1], vr[4*p+2], vr[4*p+3],
                      vb + (s*16*VH + p*16)*2);
            #pragma unroll
            for (int mh = 0; mh < 2; mh++) {
                unsigned a0 = pkh2(sacc[mh][2*s][0],   sacc[mh][2*s][1]);
                unsigned a1 = pkh2(sacc[mh][2*s][2],   sacc[mh][2*s][3]);
                unsigned a2 = pkh2(sacc[mh][2*s+1][0], sacc[mh][2*s+1][1]);
                unsigned a3 = pkh2(sacc[mh][2*s+1][2], sacc[mh][2*s+1][3]);
                #pragma unroll
                for (int p = 0; p < 4; p++) {
                    mma16(oacc[mh][2*p],   a0, a1, a2, a3, vr[4*p],   vr[4*p+1]);
                    mma16(oacc[mh][2*p+1], a0, a1, a2, a3, vr[4*p+2], vr[4*p+3]);
                }
            }
        }

        if (kc + 2 < nch) {
            __syncthreads();
            ISSUE_KV(kc + 2, buf);
        }
    }
    #undef ISSUE_KV

    // ---- normalize and write out (B, S, H*D), float2 stores ----
    #pragma unroll
    for (int mh = 0; mh < 2; mh++) {
        float la = lm[mh][0], lb = lm[mh][1];
        la += __shfl_xor_sync(FULL, la, 1);
        la += __shfl_xor_sync(FULL, la, 2);
        lb += __shfl_xor_sync(FULL, lb, 1);
        lb += __shfl_xor_sync(FULL, lb, 2);
        float inv0 = 1.0f / la;
        float inv1 = 1.0f / lb;

        const int qa = q0 + wm + mh*16 + g;
        const int qb = qa + 8;
        #pragma unroll
        for (int dj = 0; dj < 8; dj++) {
            int d = h*HDIM + dj*8 + 2*t;
            float2 v0 = make_float2(oacc[mh][dj][0]*inv0, oacc[mh][dj][1]*inv0);
            float2 v1 = make_float2(oacc[mh][dj][2]*inv1, oacc[mh][dj][3]*inv1);
            *reinterpret_cast<float2*>(&out[(b*SEQ + qa)*EMB + d]) = v0;
            *reinterpret_cast<float2*>(&out[(b*SEQ + qb)*EMB + d]) = v1;
        }
    }
}

// ---------------------------------------------------------------------------
extern "C" void kernel_launch(void* const* d_in, const int* in_sizes, int n_in,
                              void* d_out, int out_size)
{
    const float* inp  = (const float*)d_in[0];
    const float* mask = (const float*)d_in[1];
    const float* Wq   = (const float*)d_in[2];
    const float* bq   = (const float*)d_in[3];
    const float* Wk   = (const float*)d_in[4];
    const float* bk   = (const float*)d_in[5];
    const float* Wv   = (const float*)d_in[6];
    const float* bv   = (const float*)d_in[7];
    float* out = (float*)d_out;

    cudaFuncSetAttribute(qkv_proj,
                         cudaFuncAttributeMaxDynamicSharedMemorySize,
                         (int)PROJ_SMEM);
    cudaFuncSetAttribute(attn_kernel,
                         cudaFuncAttributeMaxDynamicSharedMemorySize,
                         (int)ATTN_SMEM);

    setup_kernel<<<NB_SETUP, 256>>>(inp, mask, Wq, Wk, Wv);

    dim3 gproj(EMB/128, 64, 3);
    qkv_proj<<<gproj, 128, PROJ_SMEM>>>(bq, bk, bv);

    dim3 gattn(SEQ/128, HEADS, BATCH);
    attn_kernel<<<gattn, 128, ATTN_SMEM>>>(out);
}